// round 2
// baseline (speedup 1.0000x reference)
#include <cuda_runtime.h>

#define BATCH 16
#define CIN   256
#define HW    4096
#define DDIM  128
#define CC    32
#define EPSV  1e-8f
#define NF    ((long)BATCH * CIN * HW)   // 16777216 f_out elements

__device__ float g_bias[BATCH * CIN];
__device__ float g_kld[BATCH];

// ---------------------------------------------------------------------------
// Kernel A: per-batch KL pipeline + bias GEMV.  16 blocks x 256 threads.
// ---------------------------------------------------------------------------
__global__ void small_kernel(const float* __restrict__ mu_prior,
                             const float* __restrict__ ls_prior,
                             const float* __restrict__ pi_prior,
                             const float* __restrict__ mu_post,
                             const float* __restrict__ ls_post,
                             const float* __restrict__ noise_c,
                             const float* __restrict__ noise_z,
                             const float* __restrict__ W,
                             const float* __restrict__ pb)
{
    int b = blockIdx.x;
    int t = threadIdx.x;

    __shared__ float s_zpost[DDIM], s_zc[DDIM], s_lspo[DDIM], s_e2po[DDIM],
                     s_mupo[DDIM], s_kstd[DDIM];
    __shared__ float s_lp[CC], s_klg[CC];

    if (t < DDIM) {
        float mu = mu_post[b * DDIM + t];
        float ls = ls_post[b * DDIM + t];
        float e  = expf(ls);
        s_mupo[t] = mu;
        s_lspo[t] = ls;
        s_e2po[t] = e * e;
        s_zpost[t] = mu + e * noise_c[b * DDIM + t];
        s_zc[t]    = mu + (e + EPSV) * noise_z[b * DDIM + t];
        s_kstd[t]  = -ls + 0.5f * (e * e + mu * mu) - 0.5f;
    }
    __syncthreads();

    int w = t >> 5, lane = t & 31;
    // each warp handles 4 clusters; lanes stride over D
    #pragma unroll
    for (int i = 0; i < 4; i++) {
        int c = w * 4 + i;
        float lp = 0.f, klg = 0.f;
        for (int dd = lane; dd < DDIM; dd += 32) {
            int idx = (b * DDIM + dd) * CC + c;
            float mpr = mu_prior[idx];
            float lpr = ls_prior[idx];
            float s2  = expf(2.f * lpr);           // sigma_prior^2
            float dz  = s_zpost[dd] - mpr;
            lp += -lpr - 0.91893853320467274f - dz * dz / (2.f * s2);
            float dm = s_mupo[dd] - mpr;
            klg += lpr - s_lspo[dd]
                 + (s_e2po[dd] + dm * dm) / (2.f * s2 + EPSV) - 0.5f;
        }
        #pragma unroll
        for (int o = 16; o; o >>= 1) {
            lp  += __shfl_xor_sync(0xffffffffu, lp,  o);
            klg += __shfl_xor_sync(0xffffffffu, klg, o);
        }
        if (lane == 0) { s_lp[c] = lp; s_klg[c] = klg; }
    }
    __syncthreads();

    if (w == 0) {
        int c = lane;                 // C == 32 == warp size
        float lp = s_lp[c];
        float m = lp;
        #pragma unroll
        for (int o = 16; o; o >>= 1) m = fmaxf(m, __shfl_xor_sync(0xffffffffu, m, o));
        float e = expf(lp - m);
        float s = e;
        #pragma unroll
        for (int o = 16; o; o >>= 1) s += __shfl_xor_sync(0xffffffffu, s, o);
        float pi = e / s;
        float term = pi * s_klg[c]
                   + pi * (logf(pi + EPSV) - logf(pi_prior[b * CC + c] + EPSV));
        #pragma unroll
        for (int o = 16; o; o >>= 1) term += __shfl_xor_sync(0xffffffffu, term, o);
        float ks = s_kstd[lane] + s_kstd[lane + 32] + s_kstd[lane + 64] + s_kstd[lane + 96];
        #pragma unroll
        for (int o = 16; o; o >>= 1) ks += __shfl_xor_sync(0xffffffffu, ks, o);
        if (lane == 0) g_kld[b] = term + ks;
    }

    // bias[b][o] = sum_d z_c[d] * Wz[o][d] + pb[o];  Wz = W[:, 256:384]
    {
        int o = t;
        float acc = 0.f;
        const float* wr = W + (long)o * 384 + 256;
        #pragma unroll
        for (int dd = 0; dd < DDIM; dd += 4) {
            float4 wv = *(const float4*)(wr + dd);
            acc += wv.x * s_zc[dd] + wv.y * s_zc[dd + 1]
                 + wv.z * s_zc[dd + 2] + wv.w * s_zc[dd + 3];
        }
        g_bias[b * CIN + o] = acc + pb[o];
    }
}

// ---------------------------------------------------------------------------
// Packed f32x2 helpers (ptxas never auto-fuses FFMA2; B300 f32x2 = 2x FFMA tput)
// ---------------------------------------------------------------------------
__device__ __forceinline__ unsigned long long pack2(float lo, float hi) {
    unsigned long long r;
    asm("mov.b64 %0, {%1,%2};" : "=l"(r) : "f"(lo), "f"(hi));
    return r;
}
__device__ __forceinline__ void fma2(unsigned long long& acc,
                                     unsigned long long a, unsigned long long b) {
    asm("fma.rn.f32x2 %0, %1, %2, %0;" : "+l"(acc) : "l"(a), "l"(b));
}

// ---------------------------------------------------------------------------
// Kernel B: f_out[b,o,p] = sum_c Wf[o,c] * f[b,c,p] + bias[b,o]
// 128(O) x 128(P) tile per block, 256 threads, 8x8 micro-tile, f32x2 math.
// ---------------------------------------------------------------------------
__global__ __launch_bounds__(256, 2)
void gemm_kernel(const float* __restrict__ f, const float* __restrict__ W,
                 float* __restrict__ out)
{
    const int p0 = blockIdx.x * 128;
    const int o0 = blockIdx.y * 128;
    const int b  = blockIdx.z;

    __shared__ float sW[8][128];   // [k][o]
    __shared__ float sF[8][128];   // [k][p]

    const int t  = threadIdx.x;
    const int tx = t & 15;         // p micro index
    const int ty = t >> 4;         // o micro index

    unsigned long long acc[8][4];
    #pragma unroll
    for (int i = 0; i < 8; i++)
        #pragma unroll
        for (int j = 0; j < 4; j++) acc[i][j] = 0ull;

    const float* fb = f + (long)b * CIN * HW;

    const int wo = t >> 1;            // 0..127 : o within tile
    const int wc = (t & 1) * 4;       // 0 or 4 : c sub-chunk
    const int fc = t >> 5;            // 0..7   : c within chunk
    const int fp = (t & 31) * 4;      // p within tile

    for (int c0 = 0; c0 < CIN; c0 += 8) {
        float4 wv = *(const float4*)(W + (long)(o0 + wo) * 384 + c0 + wc);
        float4 fv = *(const float4*)(fb + (long)(c0 + fc) * HW + p0 + fp);
        __syncthreads();
        sW[wc + 0][wo] = wv.x;
        sW[wc + 1][wo] = wv.y;
        sW[wc + 2][wo] = wv.z;
        sW[wc + 3][wo] = wv.w;
        *(float4*)&sF[fc][fp] = fv;
        __syncthreads();

        #pragma unroll
        for (int k = 0; k < 8; k++) {
            float4 a0 = *(const float4*)&sW[k][ty * 8];
            float4 a1 = *(const float4*)&sW[k][ty * 8 + 4];
            float4 b0 = *(const float4*)&sF[k][tx * 8];
            float4 b1 = *(const float4*)&sF[k][tx * 8 + 4];
            unsigned long long bp0 = pack2(b0.x, b0.y);
            unsigned long long bp1 = pack2(b0.z, b0.w);
            unsigned long long bp2 = pack2(b1.x, b1.y);
            unsigned long long bp3 = pack2(b1.z, b1.w);
            float av[8] = {a0.x, a0.y, a0.z, a0.w, a1.x, a1.y, a1.z, a1.w};
            #pragma unroll
            for (int i = 0; i < 8; i++) {
                unsigned long long ap = pack2(av[i], av[i]);
                fma2(acc[i][0], ap, bp0);
                fma2(acc[i][1], ap, bp1);
                fma2(acc[i][2], ap, bp2);
                fma2(acc[i][3], ap, bp3);
            }
        }
    }

    // epilogue: unpack, add bias, store
    #pragma unroll
    for (int i = 0; i < 8; i++) {
        int o = o0 + ty * 8 + i;
        float bias = g_bias[b * CIN + o];
        union { unsigned long long u; float2 f2; } u0, u1, u2, u3;
        u0.u = acc[i][0]; u1.u = acc[i][1]; u2.u = acc[i][2]; u3.u = acc[i][3];
        float4 r0 = make_float4(u0.f2.x + bias, u0.f2.y + bias,
                                u1.f2.x + bias, u1.f2.y + bias);
        float4 r1 = make_float4(u2.f2.x + bias, u2.f2.y + bias,
                                u3.f2.x + bias, u3.f2.y + bias);
        float* dst = out + ((long)b * CIN + o) * HW + p0 + tx * 8;
        *(float4*)dst       = r0;
        *(float4*)(dst + 4) = r1;
    }
}

// ---------------------------------------------------------------------------
// Kernel C: reduce per-batch kld into the scalar tail of d_out.
// ---------------------------------------------------------------------------
__global__ void finalize_kernel(float* __restrict__ out, int out_size)
{
    if (threadIdx.x == 0 && blockIdx.x == 0) {
        float s = 0.f;
        #pragma unroll
        for (int b = 0; b < BATCH; b++) s += g_kld[b];
        s *= (1.f / BATCH);
        for (long i = NF; i < (long)out_size; i++) out[i] = s;
    }
}

// ---------------------------------------------------------------------------
extern "C" void kernel_launch(void* const* d_in, const int* in_sizes, int n_in,
                              void* d_out, int out_size)
{
    const float* f_curr   = (const float*)d_in[0];
    const float* mu_prior = (const float*)d_in[1];
    const float* ls_prior = (const float*)d_in[2];
    const float* pi_prior = (const float*)d_in[3];
    const float* mu_post  = (const float*)d_in[4];
    const float* ls_post  = (const float*)d_in[5];
    const float* noise_c  = (const float*)d_in[6];
    const float* noise_z  = (const float*)d_in[7];
    const float* W        = (const float*)d_in[8];
    const float* pb       = (const float*)d_in[9];
    float* out = (float*)d_out;

    small_kernel<<<BATCH, 256>>>(mu_prior, ls_prior, pi_prior, mu_post, ls_post,
                                 noise_c, noise_z, W, pb);
    dim3 grid(HW / 128, CIN / 128, BATCH);
    gemm_kernel<<<grid, 256>>>(f_curr, W, out);
    finalize_kernel<<<1, 32>>>(out, out_size);
}

// round 4
// speedup vs baseline: 1.8554x; 1.8554x over previous
#include <cuda_runtime.h>
#include <cuda_bf16.h>

#define BATCH 16
#define CIN   256
#define HW    4096
#define DDIM  128
#define CCL   32
#define EPSV  1e-8f
#define NF    ((long)BATCH * CIN * HW)

#define KC    32
#define NCH   8      // 256 / 32 k-chunks

// ---- GEMM smem layout (bytes) ----
#define OFF_STG  0            // 2 bufs x 32 rows x 132 f32 = 33792
#define STG_BUF  16896
#define OFF_BHI  33792        // 128 rows x 20 u32 = 10240
#define OFF_BLO  44032
#define OFF_AHI  54272        // 2 bufs x 256 rows x 20 u32 = 40960
#define ABUF     20480
#define OFF_ALO  95232        // 2 bufs
#define SMEM_TOTAL 136192

__device__ unsigned g_Whi[CIN * 128];   // bf16x2 pairs, [o][cpair]
__device__ unsigned g_Wlo[CIN * 128];
__device__ float    g_bias[BATCH * CIN];
__device__ float    g_kld[BATCH];
__device__ int      g_cnt;

// ---------------------------------------------------------------------------
__device__ __forceinline__ unsigned smem_u32(const void* p) {
    unsigned a;
    asm("{ .reg .u64 t; cvta.to.shared.u64 t, %1; cvt.u32.u64 %0, t; }" : "=r"(a) : "l"(p));
    return a;
}
__device__ __forceinline__ void cp16(unsigned dst, const void* src) {
    asm volatile("cp.async.cg.shared.global [%0], [%1], 16;" :: "r"(dst), "l"(src));
}
#define CP_COMMIT() asm volatile("cp.async.commit_group;")
#define CP_WAIT0()  asm volatile("cp.async.wait_group 0;")

__device__ __forceinline__ unsigned lds32(unsigned a) {
    unsigned v;
    asm volatile("ld.shared.b32 %0, [%1];" : "=r"(v) : "r"(a));
    return v;
}
#define STS128(a, r0, r1, r2, r3) \
    asm volatile("st.shared.v4.b32 [%0], {%1,%2,%3,%4};" :: "r"(a), "r"(r0), "r"(r1), "r"(r2), "r"(r3) : "memory")

// exact split of two fp32 into bf16x2 hi (truncated) + bf16x2 lo (residual, rn)
__device__ __forceinline__ void split2(float a, float b, unsigned& hi, unsigned& lo) {
    unsigned ua = __float_as_uint(a), ub = __float_as_uint(b);
    hi = __byte_perm(ua, ub, 0x7632);                   // {lo16: a_hi, hi16: b_hi}
    float alo = a - __uint_as_float(ua & 0xFFFF0000u);  // exact residual
    float blo = b - __uint_as_float(ub & 0xFFFF0000u);
    asm("cvt.rn.bf16x2.f32 %0, %1, %2;" : "=r"(lo) : "f"(blo), "f"(alo));  // low half = alo
}

__device__ __forceinline__ void mma_bf16(float* c, unsigned a0, unsigned a1,
                                         unsigned a2, unsigned a3,
                                         unsigned b0, unsigned b1) {
    asm volatile(
        "mma.sync.aligned.m16n8k16.row.col.f32.bf16.bf16.f32 "
        "{%0,%1,%2,%3}, {%4,%5,%6,%7}, {%8,%9}, {%0,%1,%2,%3};"
        : "+f"(c[0]), "+f"(c[1]), "+f"(c[2]), "+f"(c[3])
        : "r"(a0), "r"(a1), "r"(a2), "r"(a3), "r"(b0), "r"(b1));
}

// ---------------------------------------------------------------------------
// Prepass: blocks 0..15 -> per-batch KLD + bias; blocks 16..47 -> W bf16 split
// ---------------------------------------------------------------------------
__global__ void prepass_kernel(const float* __restrict__ mu_prior,
                               const float* __restrict__ ls_prior,
                               const float* __restrict__ pi_prior,
                               const float* __restrict__ mu_post,
                               const float* __restrict__ ls_post,
                               const float* __restrict__ noise_c,
                               const float* __restrict__ noise_z,
                               const float* __restrict__ W,
                               const float* __restrict__ pb,
                               float* __restrict__ out, int out_size)
{
    const int t = threadIdx.x;
    const int wid = t >> 5, lane = t & 31;

    if (blockIdx.x >= BATCH) {
        // ---- W conversion: block j handles 8 o-rows ----
        const int j = blockIdx.x - BATCH;
        const int o = j * 8 + wid;
        const float* wr = W + (long)o * 384 + lane * 8;
        float4 f0 = *(const float4*)(wr);
        float4 f1 = *(const float4*)(wr + 4);
        unsigned hi[4], lo[4];
        split2(f0.x, f0.y, hi[0], lo[0]);
        split2(f0.z, f0.w, hi[1], lo[1]);
        split2(f1.x, f1.y, hi[2], lo[2]);
        split2(f1.z, f1.w, hi[3], lo[3]);
        *(uint4*)&g_Whi[o * 128 + lane * 4] = make_uint4(hi[0], hi[1], hi[2], hi[3]);
        *(uint4*)&g_Wlo[o * 128 + lane * 4] = make_uint4(lo[0], lo[1], lo[2], lo[3]);
        return;
    }

    // ---- KLD + bias for batch b ----
    const int b = blockIdx.x;
    __shared__ float zpost[DDIM], mupo[DDIM], lspo[DDIM], e2po[DDIM], kstd[DDIM], zc[DDIM];
    __shared__ float lps[256], klgs[256];

    if (t < DDIM) {
        float mu = mu_post[b * DDIM + t];
        float ls = ls_post[b * DDIM + t];
        float e  = expf(ls);
        mupo[t] = mu; lspo[t] = ls; e2po[t] = e * e;
        zpost[t] = mu + e * noise_c[b * DDIM + t];
        zc[t]    = mu + (e + EPSV) * noise_z[b * DDIM + t];
        kstd[t]  = -ls + 0.5f * (e * e + mu * mu) - 0.5f;
    }
    __syncthreads();

    const int c = lane;                      // CCL == 32
    float lp = 0.f, klg = 0.f;
    #pragma unroll 4
    for (int j = 0; j < 16; j++) {
        int dd = wid * 16 + j;
        long idx = ((long)b * DDIM + dd) * CCL + c;     // coalesced in c
        float mpr = mu_prior[idx];
        float lpr = ls_prior[idx];
        float s2x2 = 2.f * expf(2.f * lpr);
        float dz = zpost[dd] - mpr;
        lp += -lpr - 0.91893853320467274f - dz * dz / s2x2;
        float dm = mupo[dd] - mpr;
        klg += lpr - lspo[dd] + (e2po[dd] + dm * dm) / (s2x2 + EPSV) - 0.5f;
    }
    lps[wid * 32 + c] = lp; klgs[wid * 32 + c] = klg;
    __syncthreads();

    if (wid == 0) {
        float LP = 0.f, KG = 0.f;
        #pragma unroll
        for (int j = 0; j < 8; j++) { LP += lps[j * 32 + c]; KG += klgs[j * 32 + c]; }
        float m = LP;
        #pragma unroll
        for (int o = 16; o; o >>= 1) m = fmaxf(m, __shfl_xor_sync(~0u, m, o));
        float e = expf(LP - m), s = e;
        #pragma unroll
        for (int o = 16; o; o >>= 1) s += __shfl_xor_sync(~0u, s, o);
        float pi = e / s;
        float term = pi * KG + pi * (logf(pi + EPSV) - logf(pi_prior[b * CCL + c] + EPSV));
        #pragma unroll
        for (int o = 16; o; o >>= 1) term += __shfl_xor_sync(~0u, term, o);
        float ks = kstd[c] + kstd[c + 32] + kstd[c + 64] + kstd[c + 96];
        #pragma unroll
        for (int o = 16; o; o >>= 1) ks += __shfl_xor_sync(~0u, ks, o);
        if (c == 0) g_kld[b] = term + ks;
    }

    // bias[b][o] = z_c . Wz[o] + pb[o]
    {
        float acc = 0.f;
        const float* wz = W + (long)t * 384 + CIN;
        #pragma unroll
        for (int dd = 0; dd < DDIM; dd += 4) {
            float4 wv = *(const float4*)(wz + dd);
            acc += wv.x * zc[dd] + wv.y * zc[dd + 1] + wv.z * zc[dd + 2] + wv.w * zc[dd + 3];
        }
        g_bias[b * CIN + t] = acc + pb[t];
    }
    __syncthreads();

    if (t == 0) {
        __threadfence();
        int old = atomicAdd(&g_cnt, 1);
        if (old == BATCH - 1) {
            __threadfence();
            float s = 0.f;
            #pragma unroll
            for (int bb = 0; bb < BATCH; bb++) s += g_kld[bb];
            s *= (1.f / BATCH);
            for (long i = NF; i < (long)out_size; i++) out[i] = s;
            atomicExch(&g_cnt, 0);
        }
    }
}

// ---------------------------------------------------------------------------
// GEMM: 512 CTAs x 512 thr. Tile O=256 x P=128, k-chunks of 32.
// bf16 hi/lo split, 3-pass mma.sync m16n8k16 accumulation.
// ---------------------------------------------------------------------------
__global__ __launch_bounds__(512, 1)
void gemm_kernel(const float* __restrict__ f, float* __restrict__ out)
{
    extern __shared__ char smem[];
    const unsigned sb = smem_u32(smem);
    const int t = threadIdx.x;
    const int wid = t >> 5, lane = t & 31;
    const int b  = blockIdx.x >> 5;
    const int p0 = (blockIdx.x & 31) << 7;

    const float* fb = f + (long)b * CIN * HW + p0;

    // ---- prefetch issue for chunk ch into parity par ----
    auto issue_chunk = [&](int ch, int par) {
        unsigned stg = sb + OFF_STG + par * STG_BUF;
        #pragma unroll
        for (int j = 0; j < 2; j++) {
            int id = t + j * 512, row = id >> 5, seg = id & 31;
            cp16(stg + row * 528 + seg * 16,
                 fb + (long)(ch * KC + row) * HW + seg * 4);
        }
        #pragma unroll
        for (int j = 0; j < 4; j++) {
            int id = t + j * 512;
            int half = j >> 1;                  // 0 = hi, 1 = lo
            int idx = id & 1023, o = idx >> 2, seg = idx & 3;
            const unsigned* src = (half ? g_Wlo : g_Whi) + o * 128 + ch * 16 + seg * 4;
            cp16(sb + (half ? OFF_ALO : OFF_AHI) + par * ABUF + o * 80 + seg * 16, src);
        }
        CP_COMMIT();
    };

    issue_chunk(0, 0);

    float c[4][4][4];
    #pragma unroll
    for (int i = 0; i < 4; i++)
        #pragma unroll
        for (int j = 0; j < 4; j++)
            #pragma unroll
            for (int k = 0; k < 4; k++) c[i][j][k] = 0.f;

    const int wy = wid >> 2;          // o-block (64 each)
    const int wx = wid & 3;           // p-block (32 each)
    const unsigned r = lane >> 2, qq = lane & 3;
    const unsigned aoff = ((wy * 64 + r) * 20 + qq) * 4;
    const unsigned boff = ((wx * 32 + r) * 20 + qq) * 4;

    for (int ch = 0; ch < NCH; ch++) {
        const int par = ch & 1;
        CP_WAIT0();
        __syncthreads();

        // convert f chunk: transpose + split -> B operands
        {
            const float* stg = (const float*)(smem + OFF_STG + par * STG_BUF);
            const int p = t & 127, g = t >> 7;
            unsigned hw[4], lw[4];
            #pragma unroll
            for (int j = 0; j < 4; j++) {
                int kp = g * 4 + j;
                float a = stg[(2 * kp) * 132 + p];
                float q = stg[(2 * kp + 1) * 132 + p];
                split2(a, q, hw[j], lw[j]);
            }
            unsigned so = (unsigned)(p * 20 + g * 4) * 4;
            STS128(sb + OFF_BHI + so, hw[0], hw[1], hw[2], hw[3]);
            STS128(sb + OFF_BLO + so, lw[0], lw[1], lw[2], lw[3]);
        }
        __syncthreads();

        if (ch < NCH - 1) issue_chunk(ch + 1, par ^ 1);

        const unsigned Ahi_b = sb + OFF_AHI + par * ABUF + aoff;
        const unsigned Alo_b = sb + OFF_ALO + par * ABUF + aoff;
        #pragma unroll
        for (int pr = 0; pr < 3; pr++) {
            const unsigned Ab = (pr == 2) ? Alo_b : Ahi_b;
            const unsigned Bb = sb + ((pr == 1) ? OFF_BLO : OFF_BHI) + boff;
            #pragma unroll
            for (int ks = 0; ks < 2; ks++) {
                unsigned b0[4], b1[4];
                #pragma unroll
                for (int ni = 0; ni < 4; ni++) {
                    unsigned ad = Bb + ks * 32 + ni * 640;
                    b0[ni] = lds32(ad);
                    b1[ni] = lds32(ad + 16);
                }
                #pragma unroll
                for (int mi = 0; mi < 4; mi++) {
                    unsigned aad = Ab + ks * 32 + mi * 1280;
                    unsigned a0 = lds32(aad);
                    unsigned a1 = lds32(aad + 640);
                    unsigned a2 = lds32(aad + 16);
                    unsigned a3 = lds32(aad + 656);
                    #pragma unroll
                    for (int ni = 0; ni < 4; ni++)
                        mma_bf16(c[mi][ni], a0, a1, a2, a3, b0[ni], b1[ni]);
                }
            }
        }
    }

    // ---- epilogue: bias add + store ----
    #pragma unroll
    for (int mi = 0; mi < 4; mi++) {
        #pragma unroll
        for (int h = 0; h < 2; h++) {
            int o = wy * 64 + mi * 16 + (int)r + h * 8;
            float bias = g_bias[b * CIN + o];
            float* row = out + ((long)(b * CIN + o)) * HW + p0 + wx * 32 + 2 * qq;
            #pragma unroll
            for (int ni = 0; ni < 4; ni++) {
                float2 v = make_float2(c[mi][ni][2 * h] + bias,
                                       c[mi][ni][2 * h + 1] + bias);
                *(float2*)(row + ni * 8) = v;
            }
        }
    }
}

// ---------------------------------------------------------------------------
extern "C" void kernel_launch(void* const* d_in, const int* in_sizes, int n_in,
                              void* d_out, int out_size)
{
    const float* f_curr   = (const float*)d_in[0];
    const float* mu_prior = (const float*)d_in[1];
    const float* ls_prior = (const float*)d_in[2];
    const float* pi_prior = (const float*)d_in[3];
    const float* mu_post  = (const float*)d_in[4];
    const float* ls_post  = (const float*)d_in[5];
    const float* noise_c  = (const float*)d_in[6];
    const float* noise_z  = (const float*)d_in[7];
    const float* W        = (const float*)d_in[8];
    const float* pb       = (const float*)d_in[9];
    float* out = (float*)d_out;

    cudaFuncSetAttribute(gemm_kernel,
                         cudaFuncAttributeMaxDynamicSharedMemorySize, SMEM_TOTAL);

    prepass_kernel<<<BATCH + 32, 256>>>(mu_prior, ls_prior, pi_prior, mu_post,
                                        ls_post, noise_c, noise_z, W, pb,
                                        out, out_size);
    gemm_kernel<<<512, 512, SMEM_TOTAL>>>(f_curr, out);
}